// round 3
// baseline (speedup 1.0000x reference)
#include <cuda_runtime.h>
#include <math.h>
#include <stdint.h>

#define BB   8
#define TOK  327680

// ---------------- scratch ----------------
__device__ float g_t  [(size_t)TOK * 48];    // token states
__device__ float g_cat[(size_t)TOK * 96];    // channels-last concat
__device__ float g_z  [(size_t)TOK * 96];    // dwconv+LN output

__device__ __forceinline__ float gelu_exact(float v) {
    return 0.5f * v * (1.0f + erff(v * 0.70710678118654752f));
}
__device__ __forceinline__ uint32_t f2tf(float f) {
    uint32_t u;
    asm("cvt.rna.tf32.f32 %0, %1;" : "=r"(u) : "f"(f));
    return u;
}
__device__ __forceinline__ int PERM(int kk) { return 4 * (kk & 3) + (kk >> 2); }

#define MMA_TF32(c, a0, a1, a2, a3, b0, b1)                                 \
    asm volatile("mma.sync.aligned.m16n8k8.row.col.f32.tf32.tf32.f32 "     \
                 "{%0,%1,%2,%3}, {%4,%5,%6,%7}, {%8,%9}, {%0,%1,%2,%3};\n" \
                 : "+f"(c[0]), "+f"(c[1]), "+f"(c[2]), "+f"(c[3])          \
                 : "r"(a0), "r"(a1), "r"(a2), "r"(a3), "r"(b0), "r"(b1))

// =====================================================================
// F1: per-layer fused qkv GEMM + banded attention + proj GEMM + residual
// block = 16 sequences = 160 rows, 384 threads (12 warps)
// smem words: sAs[9600] sA32[7680] sW1[8640] sQKV[23040] sW2[2880] = 51840
// =====================================================================
__global__ void __launch_bounds__(384, 1) f1_layer(const float* __restrict__ qkv_w,
                                                   const float* __restrict__ qkv_b,
                                                   const float* __restrict__ proj_w,
                                                   const float* __restrict__ proj_b) {
    extern __shared__ uint32_t dyn[];
    uint32_t* sAs  = dyn;                       // tf32 A / later o  (3 slabs * 160*20)
    float*    sA32 = (float*)(dyn + 9600);      // fp32 A (residual)
    uint32_t* sW1  = dyn + 17280;               // qkv_w tf32
    float*    sQKV = (float*)(dyn + 25920);     // qkv output fp32 160x144
    uint32_t* sW2  = dyn + 48960;               // proj_w tf32

    const int tid = threadIdx.x;
    const int lane = tid & 31, warp = tid >> 5;
    const int q4 = (lane & 3) * 4;
    const size_t row0 = (size_t)blockIdx.x * 160;

    // ---- load A tile (t) ----
    for (int i = tid; i < 1920; i += 384) {
        int row = i / 12, k0 = (i % 12) * 4;
        float4 v = *(const float4*)&g_t[(row0 + row) * 48 + k0];
        *(float4*)&sA32[row * 48 + k0] = v;
        int slab = k0 >> 4, j = (k0 & 15) >> 2;
        uint32_t* d = &sAs[slab * 3200 + row * 20 + j];
        d[0] = f2tf(v.x); d[4] = f2tf(v.y); d[8] = f2tf(v.z); d[12] = f2tf(v.w);
    }
    // ---- load qkv_w (48x144) ----
    for (int i = tid; i < 1728; i += 384) {
        int k = i / 36, n0 = (i % 36) * 4;
        float4 v = *(const float4*)&qkv_w[k * 144 + n0];
        int perm = PERM(k & 15);
        uint32_t* d = &sW1[(k >> 4) * 2880 + n0 * 20 + perm];
        d[0] = f2tf(v.x); d[20] = f2tf(v.y); d[40] = f2tf(v.z); d[60] = f2tf(v.w);
    }
    // ---- load proj_w (48x48) ----
    for (int i = tid; i < 576; i += 384) {
        int k = i / 12, n0 = (i % 12) * 4;
        float4 v = *(const float4*)&proj_w[k * 48 + n0];
        int perm = PERM(k & 15);
        uint32_t* d = &sW2[(k >> 4) * 960 + n0 * 20 + perm];
        d[0] = f2tf(v.x); d[20] = f2tf(v.y); d[40] = f2tf(v.z); d[60] = f2tf(v.w);
    }
    __syncthreads();

    // ---- GEMM1: 160x144 ----
    {
        const int wm = warp / 6, wn = warp % 6;
        const int R = wm * 80, C = wn * 24;
        float acc[5][3][4] = {};
#pragma unroll
        for (int s = 0; s < 3; s++) {
            uint4 af[5][2], bf[3];
#pragma unroll
            for (int a = 0; a < 5; a++) {
                int r = R + a * 16 + (lane >> 2);
                af[a][0] = *(const uint4*)&sAs[s * 3200 + r * 20 + q4];
                af[a][1] = *(const uint4*)&sAs[s * 3200 + (r + 8) * 20 + q4];
            }
#pragma unroll
            for (int n = 0; n < 3; n++)
                bf[n] = *(const uint4*)&sW1[s * 2880 + (C + n * 8 + (lane >> 2)) * 20 + q4];
#pragma unroll
            for (int a = 0; a < 5; a++)
#pragma unroll
                for (int n = 0; n < 3; n++) {
                    MMA_TF32(acc[a][n], af[a][0].x, af[a][1].x, af[a][0].y, af[a][1].y, bf[n].x, bf[n].y);
                    MMA_TF32(acc[a][n], af[a][0].z, af[a][1].z, af[a][0].w, af[a][1].w, bf[n].z, bf[n].w);
                }
        }
#pragma unroll
        for (int a = 0; a < 5; a++) {
            int r = R + a * 16 + (lane >> 2);
#pragma unroll
            for (int n = 0; n < 3; n++) {
                int c = C + n * 8 + 2 * (lane & 3);
                float b0 = qkv_b[c], b1 = qkv_b[c + 1];
                *(float2*)&sQKV[r * 144 + c]       = make_float2(acc[a][n][0] + b0, acc[a][n][1] + b1);
                *(float2*)&sQKV[(r + 8) * 144 + c] = make_float2(acc[a][n][2] + b0, acc[a][n][3] + b1);
            }
        }
    }
    __syncthreads();

    // ---- banded attention: 16 seqs x 8 heads = 128 workers ----
    if (tid < 128) {
        const int sl = tid >> 3, hh = tid & 7;
        const float* base = sQKV + sl * 1440;
        const float scale = 0.40824829046386301637f;
        for (int i = 0; i < 10; i++) {
            const float* ki = base + i * 144 + 48 + hh * 6;
            int jlo = (i > 0) ? i - 1 : 0;
            int jhi = (i < 9) ? i + 1 : 9;
            float lg[3];
            float mx = -1e30f;
            for (int j = jlo; j <= jhi; j++) {
                const float* qj = base + j * 144 + hh * 6;
                float d = 0.f;
#pragma unroll
                for (int dd = 0; dd < 6; dd++) d += ki[dd] * qj[dd];
                d *= scale;
                lg[j - jlo] = d;
                mx = fmaxf(mx, d);
            }
            float se = 0.f;
            for (int j = jlo; j <= jhi; j++) {
                lg[j - jlo] = expf(lg[j - jlo] - mx);
                se += lg[j - jlo];
            }
            float inv = 1.f / se;
            int row = sl * 10 + i;
#pragma unroll
            for (int dd = 0; dd < 6; dd++) {
                float o = 0.f;
                for (int j = jlo; j <= jhi; j++)
                    o += lg[j - jlo] * base[j * 144 + 96 + hh * 6 + dd];
                o *= inv;
                int col = hh * 6 + dd;
                sAs[(col >> 4) * 3200 + row * 20 + PERM(col & 15)] = f2tf(o);
            }
        }
    }
    __syncthreads();

    // ---- GEMM2: o(160x48) @ proj_w + bias + residual -> g_t ----
    {
        const int wm = warp & 1, wn = warp >> 1;   // wm 0..1, wn 0..5
        const int R = wm * 80, C = wn * 8;
        float acc[5][4] = {};
#pragma unroll
        for (int s = 0; s < 3; s++) {
            uint4 af[5][2];
#pragma unroll
            for (int a = 0; a < 5; a++) {
                int r = R + a * 16 + (lane >> 2);
                af[a][0] = *(const uint4*)&sAs[s * 3200 + r * 20 + q4];
                af[a][1] = *(const uint4*)&sAs[s * 3200 + (r + 8) * 20 + q4];
            }
            uint4 bf = *(const uint4*)&sW2[s * 960 + (C + (lane >> 2)) * 20 + q4];
#pragma unroll
            for (int a = 0; a < 5; a++) {
                MMA_TF32(acc[a], af[a][0].x, af[a][1].x, af[a][0].y, af[a][1].y, bf.x, bf.y);
                MMA_TF32(acc[a], af[a][0].z, af[a][1].z, af[a][0].w, af[a][1].w, bf.z, bf.w);
            }
        }
#pragma unroll
        for (int a = 0; a < 5; a++) {
            int r = R + a * 16 + (lane >> 2);
            int c = C + 2 * (lane & 3);
            float b0 = proj_b[c], b1 = proj_b[c + 1];
            float v0 = acc[a][0] + b0 + sA32[r * 48 + c];
            float v1 = acc[a][1] + b1 + sA32[r * 48 + c + 1];
            float v2 = acc[a][2] + b0 + sA32[(r + 8) * 48 + c];
            float v3 = acc[a][3] + b1 + sA32[(r + 8) * 48 + c + 1];
            *(float2*)&g_t[(row0 + r) * 48 + c]       = make_float2(v0, v1);
            *(float2*)&g_t[(row0 + r + 8) * 48 + c]   = make_float2(v2, v3);
        }
    }
}

// =====================================================================
// F2: per-layer fused ff1+GELU -> ff2 + residual. block = 128 rows, 256 thr.
// smem words: sA[7680] sW[11520] sH[30720] = 49920
// =====================================================================
__global__ void __launch_bounds__(256, 1) f2_ff(const float* __restrict__ w1,
                                                const float* __restrict__ b1,
                                                const float* __restrict__ w2,
                                                const float* __restrict__ b2) {
    extern __shared__ uint32_t dyn[];
    uint32_t* sA = dyn;           // 3 slabs * 128*20
    uint32_t* sW = dyn + 7680;    // W1 (3*192*20) then W2 (12*48*20)
    uint32_t* sH = dyn + 19200;   // 12 slabs * 128*20
    const int tid = threadIdx.x, lane = tid & 31, warp = tid >> 5;
    const int q4 = (lane & 3) * 4;
    const size_t row0 = (size_t)blockIdx.x * 128;

    for (int i = tid; i < 1536; i += 256) {
        int row = i / 12, k0 = (i % 12) * 4;
        float4 v = *(const float4*)&g_t[(row0 + row) * 48 + k0];
        int slab = k0 >> 4, j = (k0 & 15) >> 2;
        uint32_t* d = &sA[slab * 2560 + row * 20 + j];
        d[0] = f2tf(v.x); d[4] = f2tf(v.y); d[8] = f2tf(v.z); d[12] = f2tf(v.w);
    }
    for (int i = tid; i < 2304; i += 256) {
        int k = i / 48, n0 = (i % 48) * 4;
        float4 v = *(const float4*)&w1[k * 192 + n0];
        int perm = PERM(k & 15);
        uint32_t* d = &sW[(k >> 4) * 3840 + n0 * 20 + perm];
        d[0] = f2tf(v.x); d[20] = f2tf(v.y); d[40] = f2tf(v.z); d[60] = f2tf(v.w);
    }
    __syncthreads();

    // GEMM1: 128x192 = A @ W1, gelu -> sH
    {
        const int wm = warp >> 2, wn = warp & 3;
        const int R = wm * 64, C = wn * 48;
        float acc[4][6][4] = {};
#pragma unroll
        for (int s = 0; s < 3; s++) {
            uint4 af[4][2], bf[6];
#pragma unroll
            for (int a = 0; a < 4; a++) {
                int r = R + a * 16 + (lane >> 2);
                af[a][0] = *(const uint4*)&sA[s * 2560 + r * 20 + q4];
                af[a][1] = *(const uint4*)&sA[s * 2560 + (r + 8) * 20 + q4];
            }
#pragma unroll
            for (int n = 0; n < 6; n++)
                bf[n] = *(const uint4*)&sW[s * 3840 + (C + n * 8 + (lane >> 2)) * 20 + q4];
#pragma unroll
            for (int a = 0; a < 4; a++)
#pragma unroll
                for (int n = 0; n < 6; n++) {
                    MMA_TF32(acc[a][n], af[a][0].x, af[a][1].x, af[a][0].y, af[a][1].y, bf[n].x, bf[n].y);
                    MMA_TF32(acc[a][n], af[a][0].z, af[a][1].z, af[a][0].w, af[a][1].w, bf[n].z, bf[n].w);
                }
        }
#pragma unroll
        for (int a = 0; a < 4; a++) {
            int r = R + a * 16 + (lane >> 2);
#pragma unroll
            for (int n = 0; n < 6; n++) {
                int c = C + n * 8 + 2 * (lane & 3);
                float bb0 = b1[c], bb1 = b1[c + 1];
                int s0 = (c >> 4) * 2560, p0 = PERM(c & 15);
                int s1 = ((c + 1) >> 4) * 2560, p1 = PERM((c + 1) & 15);
                sH[s0 + r * 20 + p0]       = f2tf(gelu_exact(acc[a][n][0] + bb0));
                sH[s1 + r * 20 + p1]       = f2tf(gelu_exact(acc[a][n][1] + bb1));
                sH[s0 + (r + 8) * 20 + p0] = f2tf(gelu_exact(acc[a][n][2] + bb0));
                sH[s1 + (r + 8) * 20 + p1] = f2tf(gelu_exact(acc[a][n][3] + bb1));
            }
        }
    }
    __syncthreads();
    // load W2 over W1 region
    for (int i = tid; i < 2304; i += 256) {
        int k = i / 12, n0 = (i % 12) * 4;
        float4 v = *(const float4*)&w2[k * 48 + n0];
        int perm = PERM(k & 15);
        uint32_t* d = &sW[(k >> 4) * 960 + n0 * 20 + perm];
        d[0] = f2tf(v.x); d[20] = f2tf(v.y); d[40] = f2tf(v.z); d[60] = f2tf(v.w);
    }
    __syncthreads();

    // GEMM2: 128x48, K=192
    {
        const int wm = warp >> 1, wn = warp & 1;
        const int R = wm * 32, C = wn * 24;
        float acc[2][3][4] = {};
#pragma unroll 3
        for (int s = 0; s < 12; s++) {
            uint4 af[2][2], bf[3];
#pragma unroll
            for (int a = 0; a < 2; a++) {
                int r = R + a * 16 + (lane >> 2);
                af[a][0] = *(const uint4*)&sH[s * 2560 + r * 20 + q4];
                af[a][1] = *(const uint4*)&sH[s * 2560 + (r + 8) * 20 + q4];
            }
#pragma unroll
            for (int n = 0; n < 3; n++)
                bf[n] = *(const uint4*)&sW[s * 960 + (C + n * 8 + (lane >> 2)) * 20 + q4];
#pragma unroll
            for (int a = 0; a < 2; a++)
#pragma unroll
                for (int n = 0; n < 3; n++) {
                    MMA_TF32(acc[a][n], af[a][0].x, af[a][1].x, af[a][0].y, af[a][1].y, bf[n].x, bf[n].y);
                    MMA_TF32(acc[a][n], af[a][0].z, af[a][1].z, af[a][0].w, af[a][1].w, bf[n].z, bf[n].w);
                }
        }
#pragma unroll
        for (int a = 0; a < 2; a++) {
            int r = R + a * 16 + (lane >> 2);
#pragma unroll
            for (int n = 0; n < 3; n++) {
                int c = C + n * 8 + 2 * (lane & 3);
                float bb0 = b2[c], bb1 = b2[c + 1];
                float2 t0 = *(const float2*)&g_t[(row0 + r) * 48 + c];
                float2 t1 = *(const float2*)&g_t[(row0 + r + 8) * 48 + c];
                *(float2*)&g_t[(row0 + r) * 48 + c] =
                    make_float2(acc[a][n][0] + bb0 + t0.x, acc[a][n][1] + bb1 + t0.y);
                *(float2*)&g_t[(row0 + r + 8) * 48 + c] =
                    make_float2(acc[a][n][2] + bb0 + t1.x, acc[a][n][3] + bb1 + t1.y);
            }
        }
    }
}

// =====================================================================
// F3: fused tail: pw1+GELU -> pw2, + sc GEMM, direct transposed store.
// block = 64 pixels, 256 threads. smem: sZ[7680] sWb[7680] sH[30720]
// =====================================================================
__global__ void __launch_bounds__(256, 1) f3_tail(const float* __restrict__ pw1_w,
                                                  const float* __restrict__ pw1_b,
                                                  const float* __restrict__ pw2_w,
                                                  const float* __restrict__ pw2_b,
                                                  const float* __restrict__ sc_w,
                                                  const float* __restrict__ sc_b,
                                                  float* __restrict__ out) {
    extern __shared__ uint32_t dyn[];
    uint32_t* sZ  = dyn;          // 6 slabs * 64*20 (z, later cat)
    uint32_t* sWb = dyn + 7680;   // weight staging / final sOut
    uint32_t* sH  = dyn + 15360;  // 24 slabs * 64*20
    float* sOut = (float*)(dyn + 7680);   // 64*49 floats
    const int tid = threadIdx.x, lane = tid & 31, warp = tid >> 5;
    const int q4 = (lane & 3) * 4;
    const size_t row0 = (size_t)blockIdx.x * 64;
    const int n_img = (int)(row0 >> 12);
    const int hw0 = (int)(row0 & 4095);

    for (int i = tid; i < 1536; i += 256) {
        int row = i / 24, k0 = (i % 24) * 4;
        float4 v = *(const float4*)&g_z[(row0 + row) * 96 + k0];
        int slab = k0 >> 4, j = (k0 & 15) >> 2;
        uint32_t* d = &sZ[slab * 1280 + row * 20 + j];
        d[0] = f2tf(v.x); d[4] = f2tf(v.y); d[8] = f2tf(v.z); d[12] = f2tf(v.w);
    }

    // GEMM1: 64x384, K=96, W1 staged per slab
    const int wn1 = warp;
    float acc1[4][6][4] = {};
#pragma unroll 1
    for (int s = 0; s < 6; s++) {
        __syncthreads();
        for (int i = tid; i < 1536; i += 256) {
            int kk = i / 96, n0 = (i % 96) * 4;
            float4 v = *(const float4*)&pw1_w[(s * 16 + kk) * 384 + n0];
            int perm = PERM(kk);
            uint32_t* d = &sWb[n0 * 20 + perm];
            d[0] = f2tf(v.x); d[20] = f2tf(v.y); d[40] = f2tf(v.z); d[60] = f2tf(v.w);
        }
        __syncthreads();
        uint4 af[4][2], bf[6];
#pragma unroll
        for (int a = 0; a < 4; a++) {
            int r = a * 16 + (lane >> 2);
            af[a][0] = *(const uint4*)&sZ[s * 1280 + r * 20 + q4];
            af[a][1] = *(const uint4*)&sZ[s * 1280 + (r + 8) * 20 + q4];
        }
#pragma unroll
        for (int n = 0; n < 6; n++)
            bf[n] = *(const uint4*)&sWb[(wn1 * 48 + n * 8 + (lane >> 2)) * 20 + q4];
#pragma unroll
        for (int a = 0; a < 4; a++)
#pragma unroll
            for (int n = 0; n < 6; n++) {
                MMA_TF32(acc1[a][n], af[a][0].x, af[a][1].x, af[a][0].y, af[a][1].y, bf[n].x, bf[n].y);
                MMA_TF32(acc1[a][n], af[a][0].z, af[a][1].z, af[a][0].w, af[a][1].w, bf[n].z, bf[n].w);
            }
    }
    // epilogue1 -> sH (gelu)
#pragma unroll
    for (int a = 0; a < 4; a++) {
        int r = a * 16 + (lane >> 2);
#pragma unroll
        for (int n = 0; n < 6; n++) {
            int c = wn1 * 48 + n * 8 + 2 * (lane & 3);
            float bb0 = pw1_b[c], bb1 = pw1_b[c + 1];
            int s0 = (c >> 4) * 1280, p0 = PERM(c & 15);
            int s1 = ((c + 1) >> 4) * 1280, p1 = PERM((c + 1) & 15);
            sH[s0 + r * 20 + p0]       = f2tf(gelu_exact(acc1[a][n][0] + bb0));
            sH[s1 + r * 20 + p1]       = f2tf(gelu_exact(acc1[a][n][1] + bb1));
            sH[s0 + (r + 8) * 20 + p0] = f2tf(gelu_exact(acc1[a][n][2] + bb0));
            sH[s1 + (r + 8) * 20 + p1] = f2tf(gelu_exact(acc1[a][n][3] + bb1));
        }
    }

    // GEMM2: 64x48, K=384, W2 staged per slab
    const int wm2 = warp >> 1, wn2 = warp & 1;
    float acc2[3][4] = {};
#pragma unroll 1
    for (int s = 0; s < 24; s++) {
        __syncthreads();
        for (int i = tid; i < 192; i += 256) {
            int kk = i / 12, n0 = (i % 12) * 4;
            float4 v = *(const float4*)&pw2_w[(s * 16 + kk) * 48 + n0];
            int perm = PERM(kk);
            uint32_t* d = &sWb[n0 * 20 + perm];
            d[0] = f2tf(v.x); d[20] = f2tf(v.y); d[40] = f2tf(v.z); d[60] = f2tf(v.w);
        }
        __syncthreads();
        int r = wm2 * 16 + (lane >> 2);
        uint4 af0 = *(const uint4*)&sH[s * 1280 + r * 20 + q4];
        uint4 af1 = *(const uint4*)&sH[s * 1280 + (r + 8) * 20 + q4];
        uint4 bf[3];
#pragma unroll
        for (int n = 0; n < 3; n++)
            bf[n] = *(const uint4*)&sWb[(wn2 * 24 + n * 8 + (lane >> 2)) * 20 + q4];
#pragma unroll
        for (int n = 0; n < 3; n++) {
            MMA_TF32(acc2[n], af0.x, af1.x, af0.y, af1.y, bf[n].x, bf[n].y);
            MMA_TF32(acc2[n], af0.z, af1.z, af0.w, af1.w, bf[n].z, bf[n].w);
        }
    }

    // sc phase: cat tile into sZ, scw staged per slab, accumulate into acc2
    __syncthreads();
    for (int i = tid; i < 1536; i += 256) {
        int row = i / 24, k0 = (i % 24) * 4;
        float4 v = *(const float4*)&g_cat[(row0 + row) * 96 + k0];
        int slab = k0 >> 4, j = (k0 & 15) >> 2;
        uint32_t* d = &sZ[slab * 1280 + row * 20 + j];
        d[0] = f2tf(v.x); d[4] = f2tf(v.y); d[8] = f2tf(v.z); d[12] = f2tf(v.w);
    }
#pragma unroll 1
    for (int s = 0; s < 6; s++) {
        __syncthreads();
        for (int i = tid; i < 192; i += 256) {
            int o = i / 4, j = i % 4;
            float4 v = *(const float4*)&sc_w[o * 96 + s * 16 + j * 4];
            uint32_t* d = &sWb[o * 20 + j];
            d[0] = f2tf(v.x); d[4] = f2tf(v.y); d[8] = f2tf(v.z); d[12] = f2tf(v.w);
        }
        __syncthreads();
        int r = wm2 * 16 + (lane >> 2);
        uint4 af0 = *(const uint4*)&sZ[s * 1280 + r * 20 + q4];
        uint4 af1 = *(const uint4*)&sZ[s * 1280 + (r + 8) * 20 + q4];
        uint4 bf[3];
#pragma unroll
        for (int n = 0; n < 3; n++)
            bf[n] = *(const uint4*)&sWb[(wn2 * 24 + n * 8 + (lane >> 2)) * 20 + q4];
#pragma unroll
        for (int n = 0; n < 3; n++) {
            MMA_TF32(acc2[n], af0.x, af1.x, af0.y, af1.y, bf[n].x, bf[n].y);
            MMA_TF32(acc2[n], af0.z, af1.z, af0.w, af1.w, bf[n].z, bf[n].w);
        }
    }
    __syncthreads();
    // epilogue: stage into sOut (pitch 49), then transposed coalesced store
    {
        int r = wm2 * 16 + (lane >> 2);
#pragma unroll
        for (int n = 0; n < 3; n++) {
            int c = wn2 * 24 + n * 8 + 2 * (lane & 3);
            float bb0 = pw2_b[c] + sc_b[c], bb1 = pw2_b[c + 1] + sc_b[c + 1];
            sOut[r * 49 + c]           = acc2[n][0] + bb0;
            sOut[r * 49 + c + 1]       = acc2[n][1] + bb1;
            sOut[(r + 8) * 49 + c]     = acc2[n][2] + bb0;
            sOut[(r + 8) * 49 + c + 1] = acc2[n][3] + bb1;
        }
    }
    __syncthreads();
    for (int i = tid; i < 3072; i += 256) {
        int c = i >> 6, r = i & 63;
        out[((size_t)(n_img * 48 + c)) * 4096 + hw0 + r] = sOut[r * 49 + c];
    }
}

// ---------------- transposes (unchanged) ----------------
__global__ void k_tin(const float* __restrict__ x) {
    __shared__ float sm[32][33];
    const int cf0 = blockIdx.x * 32, hw0 = blockIdx.y * 32, b = blockIdx.z;
    const int tx = threadIdx.x, ty = threadIdx.y;
#pragma unroll
    for (int yy = 0; yy < 4; yy++) {
        int cf = cf0 + ty + yy * 8;
        sm[ty + yy * 8][tx] = x[((size_t)b * 480 + cf) * 4096 + hw0 + tx];
    }
    __syncthreads();
#pragma unroll
    for (int yy = 0; yy < 4; yy++) {
        int hw = hw0 + ty + yy * 8;
        g_t[((size_t)b * 4096 + hw) * 480 + cf0 + tx] = sm[tx][ty + yy * 8];
    }
}

__global__ void k_catx(const float* __restrict__ x) {
    __shared__ float sm[32][33];
    const int c0 = blockIdx.x * 32, hw0 = blockIdx.y * 32, n = blockIdx.z;
    const int tx = threadIdx.x, ty = threadIdx.y;
#pragma unroll
    for (int yy = 0; yy < 4; yy++) {
        int c = c0 + ty + yy * 8;
        if (c < 48)
            sm[ty + yy * 8][tx] = x[((size_t)n * 48 + c) * 4096 + hw0 + tx];
    }
    __syncthreads();
#pragma unroll
    for (int yy = 0; yy < 4; yy++) {
        int hw = hw0 + ty + yy * 8;
        int c = c0 + tx;
        if (c < 48)
            g_cat[((size_t)n * 4096 + hw) * 96 + c] = sm[tx][ty + yy * 8];
    }
}

__global__ void k_catt() {
    size_t idx = (size_t)blockIdx.x * 256 + threadIdx.x;
    if (idx >= (size_t)TOK * 48) return;
    int f = (int)(idx % 48);
    size_t p = idx / 48;
    int hw = (int)(p & 4095);
    int n = (int)(p >> 12);
    int b = n / 10, s = n % 10;
    g_cat[p * 96 + 48 + f] = g_t[(((size_t)b * 4096 + hw) * 10 + s) * 48 + f];
}

// ---------------- fused dwconv + LayerNorm (warp per pixel) ----------------
__global__ void __launch_bounds__(256) k_dwln(const float* __restrict__ wdw,
                                              const float* __restrict__ bdw,
                                              const float* __restrict__ gam,
                                              const float* __restrict__ bet) {
    __shared__ float sw[864], sb[96], sg[96], sbe[96];
    for (int i = threadIdx.x; i < 864; i += 256) sw[i] = wdw[i];
    if (threadIdx.x < 96) {
        sb[threadIdx.x] = bdw[threadIdx.x];
        sg[threadIdx.x] = gam[threadIdx.x];
        sbe[threadIdx.x] = bet[threadIdx.x];
    }
    __syncthreads();
    const int lane = threadIdx.x & 31, warp = threadIdx.x >> 5;
    const size_t pix = (size_t)blockIdx.x * 8 + warp;
    const int n = (int)(pix >> 12), hw = (int)(pix & 4095);
    const int h = hw >> 6, w = hw & 63;
    const int c0 = lane, c1 = lane + 32, c2 = lane + 64;
    float a0 = sb[c0], a1 = sb[c1], a2 = sb[c2];
#pragma unroll
    for (int ky = 0; ky < 3; ky++) {
        int hh = h + ky - 1;
        if (hh < 0 || hh > 63) continue;
#pragma unroll
        for (int kx = 0; kx < 3; kx++) {
            int ww = w + kx - 1;
            if (ww < 0 || ww > 63) continue;
            const float* p = &g_cat[((size_t)n * 4096 + hh * 64 + ww) * 96];
            int wi = ky * 3 + kx;
            a0 = fmaf(p[c0], sw[c0 * 9 + wi], a0);
            a1 = fmaf(p[c1], sw[c1 * 9 + wi], a1);
            a2 = fmaf(p[c2], sw[c2 * 9 + wi], a2);
        }
    }
    float s = a0 + a1 + a2;
#pragma unroll
    for (int o = 16; o; o >>= 1) s += __shfl_xor_sync(0xffffffffu, s, o);
    float mu = s * (1.f / 96.f);
    float d0 = a0 - mu, d1 = a1 - mu, d2 = a2 - mu;
    float q = d0 * d0 + d1 * d1 + d2 * d2;
#pragma unroll
    for (int o = 16; o; o >>= 1) q += __shfl_xor_sync(0xffffffffu, q, o);
    float rs = rsqrtf(q * (1.f / 96.f) + 1e-6f);
    float* z = &g_z[pix * 96];
    z[c0] = d0 * rs * sg[c0] + sbe[c0];
    z[c1] = d1 * rs * sg[c1] + sbe[c1];
    z[c2] = d2 * rs * sg[c2] + sbe[c2];
}

// ---------------- host launcher ----------------
extern "C" void kernel_launch(void* const* d_in, const int* in_sizes, int n_in,
                              void* d_out, int out_size) {
    const float* x      = (const float*)d_in[0];
    const float* qkv_w  = (const float*)d_in[1];
    const float* qkv_b  = (const float*)d_in[2];
    const float* proj_w = (const float*)d_in[3];
    const float* proj_b = (const float*)d_in[4];
    const float* ff1_w  = (const float*)d_in[5];
    const float* ff1_b  = (const float*)d_in[6];
    const float* ff2_w  = (const float*)d_in[7];
    const float* ff2_b  = (const float*)d_in[8];
    const float* dw_w   = (const float*)d_in[9];
    const float* dw_b   = (const float*)d_in[10];
    const float* ln_g   = (const float*)d_in[11];
    const float* ln_b   = (const float*)d_in[12];
    const float* pw1_w  = (const float*)d_in[13];
    const float* pw1_b  = (const float*)d_in[14];
    const float* pw2_w  = (const float*)d_in[15];
    const float* pw2_b  = (const float*)d_in[16];
    const float* sc_w   = (const float*)d_in[17];
    const float* sc_b   = (const float*)d_in[18];
    float* out = (float*)d_out;

    static bool init = false;
    if (!init) {
        cudaFuncSetAttribute(f1_layer, cudaFuncAttributeMaxDynamicSharedMemorySize, 207360);
        cudaFuncSetAttribute(f2_ff,    cudaFuncAttributeMaxDynamicSharedMemorySize, 199680);
        cudaFuncSetAttribute(f3_tail,  cudaFuncAttributeMaxDynamicSharedMemorySize, 184320);
        init = true;
    }

    const dim3 tb32(32, 8);
    k_tin<<<dim3(15, 128, BB), tb32>>>(x);

    for (int l = 0; l < 2; l++) {
        f1_layer<<<2048, 384, 207360>>>(qkv_w + l * 6912, qkv_b + l * 144,
                                        proj_w + l * 2304, proj_b + l * 48);
        f2_ff<<<2560, 256, 199680>>>(ff1_w + l * 9216, ff1_b + l * 192,
                                     ff2_w + l * 9216, ff2_b + l * 48);
    }

    k_catx<<<dim3(2, 128, 80), tb32>>>(x);
    k_catt<<<61440, 256>>>();
    k_dwln<<<40960, 256>>>(dw_w, dw_b, ln_g, ln_b);

    f3_tail<<<5120, 256, 184320>>>(pw1_w, pw1_b, pw2_w, pw2_b, sc_w, sc_b, out);
}

// round 6
// speedup vs baseline: 1.5429x; 1.5429x over previous
#include <cuda_runtime.h>
#include <cuda_fp16.h>
#include <math.h>
#include <stdint.h>

#define BB   8
#define TOK  327680

// ---------------- scratch ----------------
__device__ float g_t  [(size_t)TOK * 48];
__device__ float g_cat[(size_t)TOK * 96];
__device__ float g_z  [(size_t)TOK * 96];
__device__ float g_h  [(size_t)TOK * 384];
__device__ float g_res[(size_t)TOK * 48];
__device__ float g_scw[96 * 48];

__device__ __forceinline__ float gelu_exact(float v) {
    return 0.5f * v * (1.0f + erff(v * 0.70710678118654752f));
}
__device__ __forceinline__ uint32_t f2tf(float f) {
    uint32_t u;
    asm("cvt.rna.tf32.f32 %0, %1;" : "=r"(u) : "f"(f));
    return u;
}
__device__ __forceinline__ int PERM(int kk) { return 4 * (kk & 3) + (kk >> 2); }

#define MMA_TF32(c, a0, a1, a2, a3, b0, b1)                                 \
    asm volatile("mma.sync.aligned.m16n8k8.row.col.f32.tf32.tf32.f32 "     \
                 "{%0,%1,%2,%3}, {%4,%5,%6,%7}, {%8,%9}, {%0,%1,%2,%3};\n" \
                 : "+f"(c[0]), "+f"(c[1]), "+f"(c[2]), "+f"(c[3])          \
                 : "r"(a0), "r"(a1), "r"(a2), "r"(a3), "r"(b0), "r"(b1))

// B fragment (2 k-slabs worth) straight from global weights W[K x ldn], col c.
__device__ __forceinline__ uint4 ldw_frag(const float* __restrict__ W, int ldn,
                                          int kb, int c) {
    uint4 r;
    r.x = f2tf(__ldg(&W[(size_t)kb * ldn + c]));
    r.y = f2tf(__ldg(&W[(size_t)(kb + 4) * ldn + c]));
    r.z = f2tf(__ldg(&W[(size_t)(kb + 8) * ldn + c]));
    r.w = f2tf(__ldg(&W[(size_t)(kb + 12) * ldn + c]));
    return r;
}

// =====================================================================
// F1: fused qkv GEMM + banded attention + proj GEMM + residual
// block = 8 sequences = 80 rows, 192 threads (6 warps), 3 blocks/SM
// =====================================================================
__global__ void __launch_bounds__(192, 3) f1_layer(const float* __restrict__ qkv_w,
                                                   const float* __restrict__ qkv_b,
                                                   const float* __restrict__ proj_w,
                                                   const float* __restrict__ proj_b) {
    __shared__ uint32_t sAs[3 * 1600];     // 3 slabs x 80 rows x 20 (A, later o)
    __shared__ __half  sQKV[80 * 144];
    const int tid = threadIdx.x, lane = tid & 31, warp = tid >> 5;
    const int m4 = lane & 3, g8 = lane >> 2;
    const size_t row0 = (size_t)blockIdx.x * 80;

    // ---- load A tile from g_t ----
#pragma unroll
    for (int i = tid; i < 960; i += 192) {
        int row = i / 12, k0 = (i % 12) * 4;
        float4 v = *(const float4*)&g_t[(row0 + row) * 48 + k0];
        uint32_t* d = &sAs[(k0 >> 4) * 1600 + row * 20 + ((k0 & 15) >> 2)];
        d[0] = f2tf(v.x); d[4] = f2tf(v.y); d[8] = f2tf(v.z); d[12] = f2tf(v.w);
    }
    __syncthreads();

    // ---- GEMM1: 80x144, warp covers 24 cols ----
    {
        const int C = warp * 24;
        float acc[5][3][4] = {};
#pragma unroll
        for (int s = 0; s < 3; s++) {
            uint4 bf[3];
#pragma unroll
            for (int n = 0; n < 3; n++)
                bf[n] = ldw_frag(qkv_w, 144, s * 16 + m4, C + n * 8 + g8);
#pragma unroll
            for (int a = 0; a < 5; a++) {
                int r = a * 16 + g8;
                uint4 af0 = *(const uint4*)&sAs[s * 1600 + r * 20 + m4 * 4];
                uint4 af1 = *(const uint4*)&sAs[s * 1600 + (r + 8) * 20 + m4 * 4];
#pragma unroll
                for (int n = 0; n < 3; n++) {
                    MMA_TF32(acc[a][n], af0.x, af1.x, af0.y, af1.y, bf[n].x, bf[n].y);
                    MMA_TF32(acc[a][n], af0.z, af1.z, af0.w, af1.w, bf[n].z, bf[n].w);
                }
            }
        }
#pragma unroll
        for (int a = 0; a < 5; a++) {
            int r = a * 16 + g8;
#pragma unroll
            for (int n = 0; n < 3; n++) {
                int c = C + n * 8 + 2 * m4;
                float b0 = qkv_b[c], b1 = qkv_b[c + 1];
                sQKV[r * 144 + c]           = __float2half(acc[a][n][0] + b0);
                sQKV[r * 144 + c + 1]       = __float2half(acc[a][n][1] + b1);
                sQKV[(r + 8) * 144 + c]     = __float2half(acc[a][n][2] + b0);
                sQKV[(r + 8) * 144 + c + 1] = __float2half(acc[a][n][3] + b1);
            }
        }
    }
    __syncthreads();

    // ---- banded attention: 8 seqs x 8 heads = 64 workers; o -> sAs (tf32) ----
    if (tid < 64) {
        const int sl = tid >> 3, hh = tid & 7;
        const __half* base = sQKV + sl * 1440;
        const float scale = 0.40824829046386301637f;
        for (int i = 0; i < 10; i++) {
            const __half* ki = base + i * 144 + 48 + hh * 6;
            int jlo = (i > 0) ? i - 1 : 0;
            int jhi = (i < 9) ? i + 1 : 9;
            float lg[3];
            float mx = -1e30f;
            for (int j = jlo; j <= jhi; j++) {
                const __half* qj = base + j * 144 + hh * 6;
                float d = 0.f;
#pragma unroll
                for (int dd = 0; dd < 6; dd++)
                    d += __half2float(ki[dd]) * __half2float(qj[dd]);
                d *= scale;
                lg[j - jlo] = d;
                mx = fmaxf(mx, d);
            }
            float se = 0.f;
            for (int j = jlo; j <= jhi; j++) {
                lg[j - jlo] = expf(lg[j - jlo] - mx);
                se += lg[j - jlo];
            }
            float inv = 1.f / se;
            int row = sl * 10 + i;
#pragma unroll
            for (int dd = 0; dd < 6; dd++) {
                float o = 0.f;
                for (int j = jlo; j <= jhi; j++)
                    o += lg[j - jlo] * __half2float(base[j * 144 + 96 + hh * 6 + dd]);
                o *= inv;
                int col = hh * 6 + dd;
                sAs[(col >> 4) * 1600 + row * 20 + PERM(col & 15)] = f2tf(o);
            }
        }
    }
    __syncthreads();

    // ---- GEMM2: o(80x48) @ proj_w + bias + residual -> g_t ----
    {
        const int C = warp * 8;
        float acc[5][4] = {};
#pragma unroll
        for (int s = 0; s < 3; s++) {
            uint4 bf = ldw_frag(proj_w, 48, s * 16 + m4, C + g8);
#pragma unroll
            for (int a = 0; a < 5; a++) {
                int r = a * 16 + g8;
                uint4 af0 = *(const uint4*)&sAs[s * 1600 + r * 20 + m4 * 4];
                uint4 af1 = *(const uint4*)&sAs[s * 1600 + (r + 8) * 20 + m4 * 4];
                MMA_TF32(acc[a], af0.x, af1.x, af0.y, af1.y, bf.x, bf.y);
                MMA_TF32(acc[a], af0.z, af1.z, af0.w, af1.w, bf.z, bf.w);
            }
        }
        const int c = C + 2 * m4;
        const float b0 = proj_b[c], b1 = proj_b[c + 1];
#pragma unroll
        for (int a = 0; a < 5; a++) {
            int r = a * 16 + g8;
            float2 t0 = *(const float2*)&g_t[(row0 + r) * 48 + c];
            float2 t1 = *(const float2*)&g_t[(row0 + r + 8) * 48 + c];
            *(float2*)&g_t[(row0 + r) * 48 + c] =
                make_float2(acc[a][0] + b0 + t0.x, acc[a][1] + b1 + t0.y);
            *(float2*)&g_t[(row0 + r + 8) * 48 + c] =
                make_float2(acc[a][2] + b0 + t1.x, acc[a][3] + b1 + t1.y);
        }
    }
}

// =====================================================================
// F2: fused ff1+GELU -> ff2 + residual. block = 32 rows, 128 threads.
// CAT: last layer writes result into g_cat (channels-last, +48) instead of g_t.
// =====================================================================
template<bool CAT>
__global__ void __launch_bounds__(128, 5) f2_ff(const float* __restrict__ w1,
                                                const float* __restrict__ b1,
                                                const float* __restrict__ w2,
                                                const float* __restrict__ b2) {
    __shared__ uint32_t sA[3 * 640];     // 3 slabs x 32 x 20
    __shared__ uint32_t sH[12 * 640];    // 12 slabs x 32 x 20
    const int tid = threadIdx.x, lane = tid & 31, warp = tid >> 5;
    const int m4 = lane & 3, g8 = lane >> 2;
    const size_t row0 = (size_t)blockIdx.x * 32;

#pragma unroll
    for (int i = tid; i < 384; i += 128) {
        int row = i / 12, k0 = (i % 12) * 4;
        float4 v = *(const float4*)&g_t[(row0 + row) * 48 + k0];
        uint32_t* d = &sA[(k0 >> 4) * 640 + row * 20 + ((k0 & 15) >> 2)];
        d[0] = f2tf(v.x); d[4] = f2tf(v.y); d[8] = f2tf(v.z); d[12] = f2tf(v.w);
    }
    __syncthreads();

    // GEMM1: 32x192, warp (wm,wn): 16 rows x 96 cols
    {
        const int R = (warp >> 1) * 16, C = (warp & 1) * 96;
        float acc[12][4] = {};
#pragma unroll
        for (int s = 0; s < 3; s++) {
            int r = R + g8;
            uint4 af0 = *(const uint4*)&sA[s * 640 + r * 20 + m4 * 4];
            uint4 af1 = *(const uint4*)&sA[s * 640 + (r + 8) * 20 + m4 * 4];
#pragma unroll
            for (int n = 0; n < 12; n++) {
                uint4 bf = ldw_frag(w1, 192, s * 16 + m4, C + n * 8 + g8);
                MMA_TF32(acc[n], af0.x, af1.x, af0.y, af1.y, bf.x, bf.y);
                MMA_TF32(acc[n], af0.z, af1.z, af0.w, af1.w, bf.z, bf.w);
            }
        }
        int r = R + g8;
#pragma unroll
        for (int n = 0; n < 12; n++) {
            int c = C + n * 8 + 2 * m4;
            float bb0 = b1[c], bb1 = b1[c + 1];
            int s0 = (c >> 4) * 640, p0 = PERM(c & 15);
            int s1 = ((c + 1) >> 4) * 640, p1 = PERM((c + 1) & 15);
            sH[s0 + r * 20 + p0]       = f2tf(gelu_exact(acc[n][0] + bb0));
            sH[s1 + r * 20 + p1]       = f2tf(gelu_exact(acc[n][1] + bb1));
            sH[s0 + (r + 8) * 20 + p0] = f2tf(gelu_exact(acc[n][2] + bb0));
            sH[s1 + (r + 8) * 20 + p1] = f2tf(gelu_exact(acc[n][3] + bb1));
        }
    }
    __syncthreads();

    // GEMM2: 32x48, K=192, warp (wm,wn): 16 rows x 24 cols
    {
        const int R = (warp >> 1) * 16, C = (warp & 1) * 24;
        float acc[3][4] = {};
#pragma unroll
        for (int s = 0; s < 12; s++) {
            int r = R + g8;
            uint4 af0 = *(const uint4*)&sH[s * 640 + r * 20 + m4 * 4];
            uint4 af1 = *(const uint4*)&sH[s * 640 + (r + 8) * 20 + m4 * 4];
#pragma unroll
            for (int n = 0; n < 3; n++) {
                uint4 bf = ldw_frag(w2, 48, s * 16 + m4, C + n * 8 + g8);
                MMA_TF32(acc[n], af0.x, af1.x, af0.y, af1.y, bf.x, bf.y);
                MMA_TF32(acc[n], af0.z, af1.z, af0.w, af1.w, bf.z, bf.w);
            }
        }
        const int r = R + g8;
        const size_t rowA = row0 + r, rowB = row0 + r + 8;
        size_t pixA = 0, pixB = 0;
        if (CAT) {
            int bA = (int)(rowA / 40960), remA = (int)(rowA % 40960);
            int bB = (int)(rowB / 40960), remB = (int)(rowB % 40960);
            pixA = ((size_t)(bA * 10 + remA % 10) * 4096 + remA / 10) * 96 + 48;
            pixB = ((size_t)(bB * 10 + remB % 10) * 4096 + remB / 10) * 96 + 48;
        }
#pragma unroll
        for (int n = 0; n < 3; n++) {
            int c = C + n * 8 + 2 * m4;
            float bb0 = b2[c], bb1 = b2[c + 1];
            float2 t0 = *(const float2*)&g_t[rowA * 48 + c];
            float2 t1 = *(const float2*)&g_t[rowB * 48 + c];
            float2 v0 = make_float2(acc[n][0] + bb0 + t0.x, acc[n][1] + bb1 + t0.y);
            float2 v1 = make_float2(acc[n][2] + bb0 + t1.x, acc[n][3] + bb1 + t1.y);
            if (CAT) {
                *(float2*)&g_cat[pixA + c] = v0;
                *(float2*)&g_cat[pixB + c] = v1;
            } else {
                *(float2*)&g_t[rowA * 48 + c] = v0;
                *(float2*)&g_t[rowB * 48 + c] = v1;
            }
        }
    }
}

// ---------------- R2-proven tiled TF32 GEMM for the tail ----------------
template<int K, int N, bool GELU, bool ACC>
__global__ void __launch_bounds__(256) gemm_mma(const float* __restrict__ A,
                                                const float* __restrict__ W,
                                                const float* __restrict__ bias,
                                                float* __restrict__ C) {
    __shared__ __align__(16) uint32_t sA[2][128 * 20];
    __shared__ __align__(16) uint32_t sB[2][48 * 20];
    const int tid  = threadIdx.x;
    const int lane = tid & 31, warp = tid >> 5;
    const int wm = warp >> 1, wn = warp & 1;
    const size_t row0 = (size_t)blockIdx.x * 128;
    const int col0 = blockIdx.y * 48;

    const int a_row = tid >> 2;
    const int a_kq  = tid & 3;
    const int b_kr  = tid / 12;
    const int b_nc  = (tid % 12) * 4;

    float acc[2][3][4] = {};
    float4 a0v, a1v, bv = make_float4(0.f, 0.f, 0.f, 0.f);

    auto LDG = [&](int s) {
        const float* Ab = A + (row0 + a_row) * K + s * 16 + a_kq * 4;
        a0v = *(const float4*)Ab;
        a1v = *(const float4*)(Ab + (size_t)64 * K);
        if (tid < 192)
            bv = *(const float4*)(W + (size_t)(s * 16 + b_kr) * N + col0 + b_nc);
    };
    auto STS = [&](int b) {
        uint32_t* da = &sA[b][a_row * 20 + a_kq];
        da[0] = f2tf(a0v.x); da[4] = f2tf(a0v.y); da[8] = f2tf(a0v.z); da[12] = f2tf(a0v.w);
        uint32_t* da2 = da + 64 * 20;
        da2[0] = f2tf(a1v.x); da2[4] = f2tf(a1v.y); da2[8] = f2tf(a1v.z); da2[12] = f2tf(a1v.w);
        if (tid < 192) {
            const int perm = PERM(b_kr & 15);
            uint32_t* db = &sB[b][b_nc * 20 + perm];
            db[0] = f2tf(bv.x); db[20] = f2tf(bv.y); db[40] = f2tf(bv.z); db[60] = f2tf(bv.w);
        }
    };
    auto COMPUTE = [&](int b) {
        uint4 af[2][2], bf[3];
#pragma unroll
        for (int m = 0; m < 2; m++) {
            const int r = wm * 32 + m * 16 + (lane >> 2);
            af[m][0] = *(const uint4*)&sA[b][r * 20 + (lane & 3) * 4];
            af[m][1] = *(const uint4*)&sA[b][(r + 8) * 20 + (lane & 3) * 4];
        }
#pragma unroll
        for (int n = 0; n < 3; n++) {
            const int nn = wn * 24 + n * 8 + (lane >> 2);
            bf[n] = *(const uint4*)&sB[b][nn * 20 + (lane & 3) * 4];
        }
#pragma unroll
        for (int m = 0; m < 2; m++)
#pragma unroll
            for (int n = 0; n < 3; n++) {
                MMA_TF32(acc[m][n], af[m][0].x, af[m][1].x, af[m][0].y, af[m][1].y, bf[n].x, bf[n].y);
                MMA_TF32(acc[m][n], af[m][0].z, af[m][1].z, af[m][0].w, af[m][1].w, bf[n].z, bf[n].w);
            }
    };

    constexpr int S = K / 16;
    LDG(0);
    STS(0);
    __syncthreads();
#pragma unroll 1
    for (int s = 0; s < S; ++s) {
        if (s + 1 < S) LDG(s + 1);
        COMPUTE(s & 1);
        if (s + 1 < S) {
            STS((s & 1) ^ 1);
            __syncthreads();
        }
    }

#pragma unroll
    for (int m = 0; m < 2; m++) {
        const size_t row = row0 + wm * 32 + m * 16 + (lane >> 2);
#pragma unroll
        for (int n = 0; n < 3; n++) {
            const int col = col0 + wn * 24 + n * 8 + ((lane & 3) << 1);
            const float b0 = bias[col], b1 = bias[col + 1];
            float v0 = acc[m][n][0] + b0;
            float v1 = acc[m][n][1] + b1;
            float v2 = acc[m][n][2] + b0;
            float v3 = acc[m][n][3] + b1;
            if (GELU) {
                v0 = gelu_exact(v0); v1 = gelu_exact(v1);
                v2 = gelu_exact(v2); v3 = gelu_exact(v3);
            }
            float* p0 = C + row * N + col;
            float* p1 = p0 + (size_t)8 * N;
            if (ACC) {
                float2 o0 = *(float2*)p0, o1 = *(float2*)p1;
                v0 += o0.x; v1 += o0.y; v2 += o1.x; v3 += o1.y;
            }
            *(float2*)p0 = make_float2(v0, v1);
            *(float2*)p1 = make_float2(v2, v3);
        }
    }
}

// ---------------- transposes ----------------
__global__ void k_tin(const float* __restrict__ x) {
    __shared__ float sm[32][33];
    const int cf0 = blockIdx.x * 32, hw0 = blockIdx.y * 32, b = blockIdx.z;
    const int tx = threadIdx.x, ty = threadIdx.y;
#pragma unroll
    for (int yy = 0; yy < 4; yy++) {
        int cf = cf0 + ty + yy * 8;
        sm[ty + yy * 8][tx] = x[((size_t)b * 480 + cf) * 4096 + hw0 + tx];
    }
    __syncthreads();
#pragma unroll
    for (int yy = 0; yy < 4; yy++) {
        int hw = hw0 + ty + yy * 8;
        g_t[((size_t)b * 4096 + hw) * 480 + cf0 + tx] = sm[tx][ty + yy * 8];
    }
}

__global__ void k_catx(const float* __restrict__ x) {
    __shared__ float sm[32][33];
    const int c0 = blockIdx.x * 32, hw0 = blockIdx.y * 32, n = blockIdx.z;
    const int tx = threadIdx.x, ty = threadIdx.y;
#pragma unroll
    for (int yy = 0; yy < 4; yy++) {
        int c = c0 + ty + yy * 8;
        if (c < 48)
            sm[ty + yy * 8][tx] = x[((size_t)n * 48 + c) * 4096 + hw0 + tx];
    }
    __syncthreads();
#pragma unroll
    for (int yy = 0; yy < 4; yy++) {
        int hw = hw0 + ty + yy * 8;
        int c = c0 + tx;
        if (c < 48)
            g_cat[((size_t)n * 4096 + hw) * 96 + c] = sm[tx][ty + yy * 8];
    }
}

__global__ void k_scw(const float* __restrict__ scw) {
    int idx = blockIdx.x * 256 + threadIdx.x;
    if (idx < 96 * 48) {
        int c = idx / 48, o = idx % 48;
        g_scw[c * 48 + o] = scw[o * 96 + c];
    }
}

__global__ void k_tout(float* __restrict__ out) {
    __shared__ float sm[32][33];
    const int hw0 = blockIdx.x * 32, c0 = blockIdx.y * 32, n = blockIdx.z;
    const int tx = threadIdx.x, ty = threadIdx.y;
#pragma unroll
    for (int yy = 0; yy < 4; yy++) {
        int c = c0 + tx;
        if (c < 48)
            sm[ty + yy * 8][tx] = g_res[((size_t)n * 4096 + hw0 + ty + yy * 8) * 48 + c];
    }
    __syncthreads();
#pragma unroll
    for (int yy = 0; yy < 4; yy++) {
        int c = c0 + ty + yy * 8;
        if (c < 48)
            out[((size_t)n * 48 + c) * 4096 + hw0 + tx] = sm[tx][ty + yy * 8];
    }
}

// ---------------- fused dwconv + LayerNorm (warp per pixel) ----------------
__global__ void __launch_bounds__(256) k_dwln(const float* __restrict__ wdw,
                                              const float* __restrict__ bdw,
                                              const float* __restrict__ gam,
                                              const float* __restrict__ bet) {
    __shared__ float sw[864], sb[96], sg[96], sbe[96];
    for (int i = threadIdx.x; i < 864; i += 256) sw[i] = wdw[i];
    if (threadIdx.x < 96) {
        sb[threadIdx.x] = bdw[threadIdx.x];
        sg[threadIdx.x] = gam[threadIdx.x];
        sbe[threadIdx.x] = bet[threadIdx.x];
    }
    __syncthreads();
    const int lane = threadIdx.x & 31, warp = threadIdx.x >> 5;
    const size_t pix = (size_t)blockIdx.x * 8 + warp;
    const int n = (int)(pix >> 12), hw = (int)(pix & 4095);
    const int h = hw >> 6, w = hw & 63;
    const int c0 = lane, c1 = lane + 32, c2 = lane + 64;
    float a0 = sb[c0], a1 = sb[c1], a2 = sb[c2];
#pragma unroll
    for (int ky = 0; ky < 3; ky++) {
        int hh = h + ky - 1;
        if (hh < 0 || hh > 63) continue;
#pragma unroll
        for (int kx = 0; kx < 3; kx++) {
            int ww = w + kx - 1;
            if (ww < 0 || ww > 63) continue;
            const float* p = &g_cat[((size_t)n * 4096 + hh * 64 + ww) * 96];
            int wi = ky * 3 + kx;
            a0 = fmaf(p[c0], sw[c0 * 9 + wi], a0);
            a1 = fmaf(p[c1], sw[c1 * 9 + wi], a1);
            a2 = fmaf(p[c2], sw[c2 * 9 + wi], a2);
        }
    }
    float s = a0 + a1 + a2;
#pragma unroll
    for (int o = 16; o; o >>= 1) s += __shfl_xor_sync(0xffffffffu, s, o);
    float mu = s * (1.f / 96.f);
    float d0 = a0 - mu, d1 = a1 - mu, d2 = a2 - mu;
    float q = d0 * d0 + d1 * d1 + d2 * d2;
#pragma unroll
    for (int o = 16; o; o >>= 1) q += __shfl_xor_sync(0xffffffffu, q, o);
    float rs = rsqrtf(q * (1.f / 96.f) + 1e-6f);
    float* z = &g_z[pix * 96];
    z[c0] = d0 * rs * sg[c0] + sbe[c0];
    z[c1] = d1 * rs * sg[c1] + sbe[c1];
    z[c2] = d2 * rs * sg[c2] + sbe[c2];
}

// ---------------- host launcher ----------------
extern "C" void kernel_launch(void* const* d_in, const int* in_sizes, int n_in,
                              void* d_out, int out_size) {
    const float* x      = (const float*)d_in[0];
    const float* qkv_w  = (const float*)d_in[1];
    const float* qkv_b  = (const float*)d_in[2];
    const float* proj_w = (const float*)d_in[3];
    const float* proj_b = (const float*)d_in[4];
    const float* ff1_w  = (const float*)d_in[5];
    const float* ff1_b  = (const float*)d_in[6];
    const float* ff2_w  = (const float*)d_in[7];
    const float* ff2_b  = (const float*)d_in[8];
    const float* dw_w   = (const float*)d_in[9];
    const float* dw_b   = (const float*)d_in[10];
    const float* ln_g   = (const float*)d_in[11];
    const float* ln_b   = (const float*)d_in[12];
    const float* pw1_w  = (const float*)d_in[13];
    const float* pw1_b  = (const float*)d_in[14];
    const float* pw2_w  = (const float*)d_in[15];
    const float* pw2_b  = (const float*)d_in[16];
    const float* sc_w   = (const float*)d_in[17];
    const float* sc_b   = (const float*)d_in[18];
    float* out = (float*)d_out;

    // device addresses of __device__ globals (host code must NOT take their
    // address directly — that was the R5 bug)
    static float *pcat = nullptr, *pz, *ph, *pres, *pscw;
    static bool init = false;
    if (!init) {
        cudaGetSymbolAddress((void**)&pcat, g_cat);
        cudaGetSymbolAddress((void**)&pz,   g_z);
        cudaGetSymbolAddress((void**)&ph,   g_h);
        cudaGetSymbolAddress((void**)&pres, g_res);
        cudaGetSymbolAddress((void**)&pscw, g_scw);
        init = true;
    }

    const dim3 tb32(32, 8);
    k_tin<<<dim3(15, 128, BB), tb32>>>(x);

    // layer 0
    f1_layer<<<4096, 192>>>(qkv_w, qkv_b, proj_w, proj_b);
    f2_ff<false><<<10240, 128>>>(ff1_w, ff1_b, ff2_w, ff2_b);
    // layer 1 (f2 writes straight into g_cat's upper 48 channels)
    f1_layer<<<4096, 192>>>(qkv_w + 6912, qkv_b + 144, proj_w + 2304, proj_b + 48);
    f2_ff<true><<<10240, 128>>>(ff1_w + 9216, ff1_b + 192, ff2_w + 9216, ff2_b + 48);

    k_catx<<<dim3(2, 128, 80), tb32>>>(x);
    k_scw<<<18, 256>>>(sc_w);
    k_dwln<<<40960, 256>>>(dw_w, dw_b, ln_g, ln_b);

    gemm_mma<96, 48, false, false><<<dim3(2560, 1), 256>>>(pcat, pscw, sc_b, pres);
    gemm_mma<96, 384, true, false><<<dim3(2560, 8), 256>>>(pz, pw1_w, pw1_b, ph);
    gemm_mma<384, 48, false, true><<<dim3(2560, 1), 256>>>(ph, pw2_w, pw2_b, pres);

    k_tout<<<dim3(128, 2, 80), tb32>>>(out);
}